// round 11
// baseline (speedup 1.0000x reference)
#include <cuda_runtime.h>
#include <cuda_fp16.h>
#include <math.h>
#include <stdint.h>

#define TOTAL 65536
#define DMODEL 512
#define EQKV   1536
#define NGRAPH 1024
#define NPG    64
#define NHEAD  8
#define HD     64
#define PADROW 65

// ------------------------------- scratch ----------------------------------
__device__ float g_qkv[(size_t)TOTAL * EQKV];
__device__ float g_att[(size_t)TOTAL * DMODEL];
__device__ __half g_xh[(size_t)TOTAL * DMODEL];
__device__ __half g_xl[(size_t)TOTAL * DMODEL];
__device__ __half g_ctxh[(size_t)TOTAL * DMODEL];
__device__ __half g_ctxl[(size_t)TOTAL * DMODEL];
__device__ __half g_inwh[(size_t)EQKV * DMODEL];
__device__ __half g_outwh[(size_t)DMODEL * DMODEL];

// ------------------------------ PTX helpers -------------------------------
__device__ __forceinline__ uint32_t smem_u32(const void* p) {
    uint32_t a;
    asm("{ .reg .u64 t; cvta.to.shared.u64 t, %1; cvt.u32.u64 %0, t; }"
        : "=r"(a) : "l"(p));
    return a;
}
#define LDSM_X4(r0, r1, r2, r3, addr) \
    asm volatile("ldmatrix.sync.aligned.m8n8.x4.shared.b16 {%0,%1,%2,%3}, [%4];" \
        : "=r"(r0), "=r"(r1), "=r"(r2), "=r"(r3) : "r"(addr))
#define LDSM_X2(r0, r1, addr) \
    asm volatile("ldmatrix.sync.aligned.m8n8.x2.shared.b16 {%0,%1}, [%2];" \
        : "=r"(r0), "=r"(r1) : "r"(addr))
#define MMA_FP16(d, a, b) \
    asm volatile("mma.sync.aligned.m16n8k16.row.col.f32.f16.f16.f32 " \
        "{%0,%1,%2,%3}, {%4,%5,%6,%7}, {%8,%9}, {%0,%1,%2,%3};" \
        : "+f"((d)[0]), "+f"((d)[1]), "+f"((d)[2]), "+f"((d)[3]) \
        : "r"((a)[0]), "r"((a)[1]), "r"((a)[2]), "r"((a)[3]), \
          "r"((b)[0]), "r"((b)[1]))
#define CP_ASYNC16(dst, src) \
    asm volatile("cp.async.cg.shared.global [%0], [%1], 16;" \
        :: "r"(dst), "l"(src) : "memory")
#define CP_COMMIT() asm volatile("cp.async.commit_group;" ::: "memory")
#define CP_WAIT(n)  asm volatile("cp.async.wait_group %0;" :: "n"(n) : "memory")

// --------------------------- conversion kernels ---------------------------
__global__ void __launch_bounds__(256) split_fp16(
    const float* __restrict__ src, __half* __restrict__ hi,
    __half* __restrict__ lo, size_t n4)
{
    size_t i = (size_t)blockIdx.x * 256 + threadIdx.x;
    if (i >= n4) return;
    float4 v = ((const float4*)src)[i];
    __half h0 = __float2half(v.x), h1 = __float2half(v.y);
    __half h2 = __float2half(v.z), h3 = __float2half(v.w);
    __half2 H0(h0, h1), H1(h2, h3);
    __half2 L0(__float2half(v.x - __half2float(h0)),
               __float2half(v.y - __half2float(h1)));
    __half2 L1(__float2half(v.z - __half2float(h2)),
               __float2half(v.w - __half2float(h3)));
    ((uint2*)hi)[i] = make_uint2(*(uint32_t*)&H0, *(uint32_t*)&H1);
    ((uint2*)lo)[i] = make_uint2(*(uint32_t*)&L0, *(uint32_t*)&L1);
}

__global__ void __launch_bounds__(256) cvt_fp16(
    const float* __restrict__ src, __half* __restrict__ dst, size_t n4)
{
    size_t i = (size_t)blockIdx.x * 256 + threadIdx.x;
    if (i >= n4) return;
    float4 v = ((const float4*)src)[i];
    __half2 H0(__float2half(v.x), __float2half(v.y));
    __half2 H1(__float2half(v.z), __float2half(v.w));
    ((uint2*)dst)[i] = make_uint2(*(uint32_t*)&H0, *(uint32_t*)&H1);
}

// ===========================================================================
// 2-pass fp16 mma.sync GEMM (EXACT R6 version — measured best, frozen)
// ===========================================================================
#define PITCH 80
#define TILEB (128 * PITCH)
#define BUFB  (3 * TILEB)
#define GEMM_SMEM (2 * BUFB)

__global__ void __launch_bounds__(256, 2) gemm_fp16(
    const __half* __restrict__ Ah, const __half* __restrict__ Al,
    const __half* __restrict__ Bh,
    const float* __restrict__ bias, float* __restrict__ C,
    int N, int K)
{
    extern __shared__ __align__(16) uint8_t smem[];
    const uint32_t smBase = smem_u32(smem);

    const int tid  = threadIdx.x;
    const int wid  = tid >> 5;
    const int lane = tid & 31;
    const int wm   = wid >> 2;
    const int wn   = wid & 3;
    const int rowBase = blockIdx.y * 128;
    const int colBase = blockIdx.x * 128;

    const int g0 = tid * 2;
    const int r0g = g0 >> 2, c0g = g0 & 3;
    const int g1 = tid * 2 + 1;
    const int r1g = g1 >> 2, c1g = g1 & 3;

    const __half* pAh = Ah + (size_t)rowBase * K;
    const __half* pAl = Al + (size_t)rowBase * K;
    const __half* pBh = Bh + (size_t)colBase * K;

    const int NC = K >> 5;

    auto loadChunk = [&](int c) {
        const int k0 = c << 5;
        const uint32_t bOff = smBase + (c & 1) * BUFB;
        const uint32_t d0 = (uint32_t)(r0g * PITCH + c0g * 16);
        const uint32_t d1 = (uint32_t)(r1g * PITCH + c1g * 16);
        const size_t s0 = (size_t)r0g * K + k0 + c0g * 8;
        const size_t s1 = (size_t)r1g * K + k0 + c1g * 8;
        CP_ASYNC16(bOff + 0 * TILEB + d0, pAh + s0);
        CP_ASYNC16(bOff + 0 * TILEB + d1, pAh + s1);
        CP_ASYNC16(bOff + 1 * TILEB + d0, pAl + s0);
        CP_ASYNC16(bOff + 1 * TILEB + d1, pAl + s1);
        CP_ASYNC16(bOff + 2 * TILEB + d0, pBh + s0);
        CP_ASYNC16(bOff + 2 * TILEB + d1, pBh + s1);
    };

    float acc[4][4][4];
    #pragma unroll
    for (int mf = 0; mf < 4; mf++)
        #pragma unroll
        for (int nf = 0; nf < 4; nf++)
            #pragma unroll
            for (int e = 0; e < 4; e++) acc[mf][nf][e] = 0.f;

    loadChunk(0);
    CP_COMMIT();

    for (int c = 0; c < NC; c++) {
        if (c + 1 < NC) {
            loadChunk(c + 1);
            CP_COMMIT();
            CP_WAIT(1);
        } else {
            CP_WAIT(0);
        }
        __syncthreads();

        const uint32_t bOff = smBase + (c & 1) * BUFB;
        const uint32_t aAh = bOff;
        const uint32_t aAl = bOff + 1 * TILEB;
        const uint32_t aBh = bOff + 2 * TILEB;

        #pragma unroll
        for (int ks = 0; ks < 2; ks++) {
            const uint32_t kcol = (uint32_t)ks * 32;
            uint32_t bh[4][2];
            #pragma unroll
            for (int nf = 0; nf < 4; nf++) {
                uint32_t brow = wn * 32 + nf * 8 + (lane & 7);
                uint32_t boff = brow * PITCH + kcol + (((uint32_t)lane >> 3) & 1) * 16;
                LDSM_X2(bh[nf][0], bh[nf][1], aBh + boff);
            }
            #pragma unroll
            for (int mf = 0; mf < 4; mf++) {
                uint32_t arow = wm * 64 + mf * 16 + (lane & 15);
                uint32_t aoff = arow * PITCH + kcol + ((uint32_t)lane >> 4) * 16;
                uint32_t ah[4], al[4];
                LDSM_X4(ah[0], ah[1], ah[2], ah[3], aAh + aoff);
                LDSM_X4(al[0], al[1], al[2], al[3], aAl + aoff);
                #pragma unroll
                for (int nf = 0; nf < 4; nf++) {
                    MMA_FP16(acc[mf][nf], ah, bh[nf]);
                    MMA_FP16(acc[mf][nf], al, bh[nf]);
                }
            }
        }
        __syncthreads();
    }

    const int er = rowBase + wm * 64 + (lane >> 2);
    const int ec = colBase + wn * 32 + (lane & 3) * 2;
    #pragma unroll
    for (int mf = 0; mf < 4; mf++) {
        #pragma unroll
        for (int nf = 0; nf < 4; nf++) {
            int row = er + mf * 16;
            int col = ec + nf * 8;
            float b0 = bias[col], b1 = bias[col + 1];
            *(float2*)&C[(size_t)row * N + col] =
                make_float2(acc[mf][nf][0] + b0, acc[mf][nf][1] + b1);
            *(float2*)&C[(size_t)(row + 8) * N + col] =
                make_float2(acc[mf][nf][2] + b0, acc[mf][nf][3] + b1);
        }
    }
}

// ===========================================================================
// Per (graph, head) attention (fp32). S/P reuse the Q buffer -> 3 smem
// arrays (49.9 KB) -> 4 CTAs/SM. ctx emitted fp16 hi/lo.
// ===========================================================================
__global__ void __launch_bounds__(256) attn_kernel()
{
    extern __shared__ float sm[];
    float* Qs = sm;                      // becomes S/P after score phase
    float* Ks = sm + 1 * 64 * PADROW;
    float* Vs = sm + 2 * 64 * PADROW;
    float* Ss = Qs;                      // alias

    int h = blockIdx.x;
    int g = blockIdx.y;
    int tid = threadIdx.x;

    size_t base = (size_t)g * NPG * EQKV + (size_t)h * HD;

    for (int i = tid; i < NPG * HD; i += 256) {
        int n = i >> 6, d = i & 63;
        size_t src = base + (size_t)n * EQKV + d;
        Qs[n * PADROW + d] = g_qkv[src];
        Ks[n * PADROW + d] = g_qkv[src + DMODEL];
        Vs[n * PADROW + d] = g_qkv[src + 2 * DMODEL];
    }
    __syncthreads();

    int tx = tid & 15, ty = tid >> 4;
    int n0 = ty * 4, m0 = tx * 4;

    // scores into registers
    float c[4][4];
    #pragma unroll
    for (int i = 0; i < 4; i++)
        #pragma unroll
        for (int j = 0; j < 4; j++) c[i][j] = 0.f;
    for (int d = 0; d < HD; d++) {
        float a[4], b[4];
        #pragma unroll
        for (int i = 0; i < 4; i++) a[i] = Qs[(n0 + i) * PADROW + d];
        #pragma unroll
        for (int j = 0; j < 4; j++) b[j] = Ks[(m0 + j) * PADROW + d];
        #pragma unroll
        for (int i = 0; i < 4; i++)
            #pragma unroll
            for (int j = 0; j < 4; j++)
                c[i][j] = fmaf(a[i], b[j], c[i][j]);
    }
    __syncthreads();   // all Q reads done before S overwrites Q buffer

    #pragma unroll
    for (int i = 0; i < 4; i++)
        #pragma unroll
        for (int j = 0; j < 4; j++)
            Ss[(n0 + i) * PADROW + m0 + j] = c[i][j] * 0.125f;
    __syncthreads();

    {
        int warp = tid >> 5, lane = tid & 31;
        for (int r = 0; r < 8; r++) {
            int n = warp * 8 + r;
            float v0 = Ss[n * PADROW + lane];
            float v1 = Ss[n * PADROW + lane + 32];
            float mx = fmaxf(v0, v1);
            #pragma unroll
            for (int o = 16; o > 0; o >>= 1)
                mx = fmaxf(mx, __shfl_xor_sync(0xffffffffu, mx, o));
            float e0 = __expf(v0 - mx);
            float e1 = __expf(v1 - mx);
            float s = e0 + e1;
            #pragma unroll
            for (int o = 16; o > 0; o >>= 1)
                s += __shfl_xor_sync(0xffffffffu, s, o);
            float inv = 1.f / s;
            Ss[n * PADROW + lane]      = e0 * inv;
            Ss[n * PADROW + lane + 32] = e1 * inv;
        }
    }
    __syncthreads();

    {
        float o[4][4];
        #pragma unroll
        for (int i = 0; i < 4; i++)
            #pragma unroll
            for (int j = 0; j < 4; j++) o[i][j] = 0.f;
        for (int m = 0; m < NPG; m++) {
            float a[4], b[4];
            #pragma unroll
            for (int i = 0; i < 4; i++) a[i] = Ss[(n0 + i) * PADROW + m];
            #pragma unroll
            for (int j = 0; j < 4; j++) b[j] = Vs[m * PADROW + m0 + j];
            #pragma unroll
            for (int i = 0; i < 4; i++)
                #pragma unroll
                for (int j = 0; j < 4; j++)
                    o[i][j] = fmaf(a[i], b[j], o[i][j]);
        }
        #pragma unroll
        for (int i = 0; i < 4; i++) {
            size_t row = (size_t)(g * NPG + n0 + i) * DMODEL + h * HD + m0;
            #pragma unroll
            for (int j = 0; j < 4; j++) {
                float v = o[i][j];
                __half hh = __float2half(v);
                g_ctxh[row + j] = hh;
                g_ctxl[row + j] = __float2half(v - __half2float(hh));
            }
        }
    }
}

// ===========================================================================
// Per-graph gate + reduction
// ===========================================================================
__global__ void __launch_bounds__(256) gate_reduce(
    const float* __restrict__ gw, const float* __restrict__ gb,
    float* __restrict__ out)
{
    __shared__ float gates[NPG];
    int g = blockIdx.x;
    const float* base = g_att + (size_t)g * NPG * DMODEL;

    int warp = threadIdx.x >> 5, lane = threadIdx.x & 31;
    for (int r = 0; r < 8; r++) {
        int n = warp * 8 + r;
        const float* row = base + (size_t)n * DMODEL;
        float s = 0.f;
        #pragma unroll
        for (int c = 0; c < DMODEL / 32; c++)
            s = fmaf(row[lane + c * 32], gw[lane + c * 32], s);
        #pragma unroll
        for (int o = 16; o > 0; o >>= 1)
            s += __shfl_xor_sync(0xffffffffu, s, o);
        if (lane == 0)
            gates[n] = 1.f / (1.f + __expf(-(s + gb[0])));
    }
    __syncthreads();

    for (int c = threadIdx.x; c < DMODEL; c += 256) {
        float acc = 0.f;
        #pragma unroll 8
        for (int n = 0; n < NPG; n++)
            acc = fmaf(gates[n], base[(size_t)n * DMODEL + c], acc);
        out[(size_t)g * DMODEL + c] = acc;
    }
}

// ===========================================================================
extern "C" void kernel_launch(void* const* d_in, const int* in_sizes, int n_in,
                              void* d_out, int out_size)
{
    const float* x      = (const float*)d_in[0];
    const float* in_w   = (const float*)d_in[2];
    const float* in_b   = (const float*)d_in[3];
    const float* out_w  = (const float*)d_in[4];
    const float* out_b  = (const float*)d_in[5];
    const float* gate_w = (const float*)d_in[6];
    const float* gate_b = (const float*)d_in[7];
    float* out          = (float*)d_out;

    float *qkv, *att;
    __half *xh, *xl, *ctxh, *ctxl, *inwh, *outwh;
    cudaGetSymbolAddress((void**)&qkv, g_qkv);
    cudaGetSymbolAddress((void**)&att, g_att);
    cudaGetSymbolAddress((void**)&xh, g_xh);
    cudaGetSymbolAddress((void**)&xl, g_xl);
    cudaGetSymbolAddress((void**)&ctxh, g_ctxh);
    cudaGetSymbolAddress((void**)&ctxl, g_ctxl);
    cudaGetSymbolAddress((void**)&inwh, g_inwh);
    cudaGetSymbolAddress((void**)&outwh, g_outwh);

    const int smem_attn = 3 * 64 * PADROW * sizeof(float);   // 49920 B
    cudaFuncSetAttribute(attn_kernel,
                         cudaFuncAttributeMaxDynamicSharedMemorySize, smem_attn);
    cudaFuncSetAttribute(gemm_fp16,
                         cudaFuncAttributeMaxDynamicSharedMemorySize, GEMM_SMEM);

    // 0) operand conversion
    {
        size_t n4 = (size_t)TOTAL * DMODEL / 4;
        split_fp16<<<(unsigned)((n4 + 255) / 256), 256>>>(x, xh, xl, n4);
        size_t w4 = (size_t)EQKV * DMODEL / 4;
        cvt_fp16<<<(unsigned)((w4 + 255) / 256), 256>>>(in_w, inwh, w4);
        size_t o4 = (size_t)DMODEL * DMODEL / 4;
        cvt_fp16<<<(unsigned)((o4 + 255) / 256), 256>>>(out_w, outwh, o4);
    }

    // 1) QKV projection
    gemm_fp16<<<dim3(EQKV / 128, TOTAL / 128), 256, GEMM_SMEM>>>(
        xh, xl, inwh, in_b, qkv, EQKV, DMODEL);

    // 2) attention (fp32, emits ctx pre-split fp16)
    attn_kernel<<<dim3(NHEAD, NGRAPH), 256, smem_attn>>>();

    // 3) output projection
    gemm_fp16<<<dim3(DMODEL / 128, TOTAL / 128), 256, GEMM_SMEM>>>(
        ctxh, ctxl, outwh, out_b, att, DMODEL, DMODEL);

    // 4) gate + per-graph reduction
    gate_reduce<<<NGRAPH, 256>>>(gate_w, gate_b, out);
}

// round 13
// speedup vs baseline: 1.5469x; 1.5469x over previous
#include <cuda_runtime.h>
#include <cuda_fp16.h>
#include <math.h>
#include <stdint.h>

#define TOTAL 65536
#define DMODEL 512
#define EQKV   1536
#define NGRAPH 1024
#define NPG    64
#define NHEAD  8
#define HD     64
#define PADROW 65

// ------------------------------- scratch ----------------------------------
__device__ float g_qkv[(size_t)TOTAL * EQKV];
__device__ float g_att[(size_t)TOTAL * DMODEL];
__device__ __half g_xh[(size_t)TOTAL * DMODEL];
__device__ __half g_xl[(size_t)TOTAL * DMODEL];
__device__ __half g_ctxh[(size_t)TOTAL * DMODEL];
__device__ __half g_ctxl[(size_t)TOTAL * DMODEL];
__device__ __half g_inwh[(size_t)EQKV * DMODEL];
__device__ __half g_outwh[(size_t)DMODEL * DMODEL];

// ------------------------------ PTX helpers -------------------------------
__device__ __forceinline__ uint32_t smem_u32(const void* p) {
    uint32_t a;
    asm("{ .reg .u64 t; cvta.to.shared.u64 t, %1; cvt.u32.u64 %0, t; }"
        : "=r"(a) : "l"(p));
    return a;
}
#define LDSM_X4(r0, r1, r2, r3, addr) \
    asm volatile("ldmatrix.sync.aligned.m8n8.x4.shared.b16 {%0,%1,%2,%3}, [%4];" \
        : "=r"(r0), "=r"(r1), "=r"(r2), "=r"(r3) : "r"(addr))
#define LDSM_X2(r0, r1, addr) \
    asm volatile("ldmatrix.sync.aligned.m8n8.x2.shared.b16 {%0,%1}, [%2];" \
        : "=r"(r0), "=r"(r1) : "r"(addr))
#define MMA_FP16(d, a, b) \
    asm volatile("mma.sync.aligned.m16n8k16.row.col.f32.f16.f16.f32 " \
        "{%0,%1,%2,%3}, {%4,%5,%6,%7}, {%8,%9}, {%0,%1,%2,%3};" \
        : "+f"((d)[0]), "+f"((d)[1]), "+f"((d)[2]), "+f"((d)[3]) \
        : "r"((a)[0]), "r"((a)[1]), "r"((a)[2]), "r"((a)[3]), \
          "r"((b)[0]), "r"((b)[1]))
#define CP_ASYNC16(dst, src) \
    asm volatile("cp.async.cg.shared.global [%0], [%1], 16;" \
        :: "r"(dst), "l"(src) : "memory")
#define CP_COMMIT() asm volatile("cp.async.commit_group;" ::: "memory")
#define CP_WAIT(n)  asm volatile("cp.async.wait_group %0;" :: "n"(n) : "memory")

// --------------------------- conversion kernels ---------------------------
__global__ void __launch_bounds__(256) split_fp16(
    const float* __restrict__ src, __half* __restrict__ hi,
    __half* __restrict__ lo, size_t n4)
{
    size_t i = (size_t)blockIdx.x * 256 + threadIdx.x;
    if (i >= n4) return;
    float4 v = ((const float4*)src)[i];
    __half h0 = __float2half(v.x), h1 = __float2half(v.y);
    __half h2 = __float2half(v.z), h3 = __float2half(v.w);
    __half2 H0(h0, h1), H1(h2, h3);
    __half2 L0(__float2half(v.x - __half2float(h0)),
               __float2half(v.y - __half2float(h1)));
    __half2 L1(__float2half(v.z - __half2float(h2)),
               __float2half(v.w - __half2float(h3)));
    ((uint2*)hi)[i] = make_uint2(*(uint32_t*)&H0, *(uint32_t*)&H1);
    ((uint2*)lo)[i] = make_uint2(*(uint32_t*)&L0, *(uint32_t*)&L1);
}

__global__ void __launch_bounds__(256) cvt_fp16(
    const float* __restrict__ src, __half* __restrict__ dst, size_t n4)
{
    size_t i = (size_t)blockIdx.x * 256 + threadIdx.x;
    if (i >= n4) return;
    float4 v = ((const float4*)src)[i];
    __half2 H0(__float2half(v.x), __float2half(v.y));
    __half2 H1(__float2half(v.z), __float2half(v.w));
    ((uint2*)dst)[i] = make_uint2(*(uint32_t*)&H0, *(uint32_t*)&H1);
}

// ===========================================================================
// 2-pass fp16 mma.sync GEMM (EXACT R6 version — measured best, frozen)
// ===========================================================================
#define PITCH 80
#define TILEB (128 * PITCH)
#define BUFB  (3 * TILEB)
#define GEMM_SMEM (2 * BUFB)

__global__ void __launch_bounds__(256, 2) gemm_fp16(
    const __half* __restrict__ Ah, const __half* __restrict__ Al,
    const __half* __restrict__ Bh,
    const float* __restrict__ bias, float* __restrict__ C,
    int N, int K)
{
    extern __shared__ __align__(16) uint8_t smem[];
    const uint32_t smBase = smem_u32(smem);

    const int tid  = threadIdx.x;
    const int wid  = tid >> 5;
    const int lane = tid & 31;
    const int wm   = wid >> 2;
    const int wn   = wid & 3;
    const int rowBase = blockIdx.y * 128;
    const int colBase = blockIdx.x * 128;

    const int g0 = tid * 2;
    const int r0g = g0 >> 2, c0g = g0 & 3;
    const int g1 = tid * 2 + 1;
    const int r1g = g1 >> 2, c1g = g1 & 3;

    const __half* pAh = Ah + (size_t)rowBase * K;
    const __half* pAl = Al + (size_t)rowBase * K;
    const __half* pBh = Bh + (size_t)colBase * K;

    const int NC = K >> 5;

    auto loadChunk = [&](int c) {
        const int k0 = c << 5;
        const uint32_t bOff = smBase + (c & 1) * BUFB;
        const uint32_t d0 = (uint32_t)(r0g * PITCH + c0g * 16);
        const uint32_t d1 = (uint32_t)(r1g * PITCH + c1g * 16);
        const size_t s0 = (size_t)r0g * K + k0 + c0g * 8;
        const size_t s1 = (size_t)r1g * K + k0 + c1g * 8;
        CP_ASYNC16(bOff + 0 * TILEB + d0, pAh + s0);
        CP_ASYNC16(bOff + 0 * TILEB + d1, pAh + s1);
        CP_ASYNC16(bOff + 1 * TILEB + d0, pAl + s0);
        CP_ASYNC16(bOff + 1 * TILEB + d1, pAl + s1);
        CP_ASYNC16(bOff + 2 * TILEB + d0, pBh + s0);
        CP_ASYNC16(bOff + 2 * TILEB + d1, pBh + s1);
    };

    float acc[4][4][4];
    #pragma unroll
    for (int mf = 0; mf < 4; mf++)
        #pragma unroll
        for (int nf = 0; nf < 4; nf++)
            #pragma unroll
            for (int e = 0; e < 4; e++) acc[mf][nf][e] = 0.f;

    loadChunk(0);
    CP_COMMIT();

    for (int c = 0; c < NC; c++) {
        if (c + 1 < NC) {
            loadChunk(c + 1);
            CP_COMMIT();
            CP_WAIT(1);
        } else {
            CP_WAIT(0);
        }
        __syncthreads();

        const uint32_t bOff = smBase + (c & 1) * BUFB;
        const uint32_t aAh = bOff;
        const uint32_t aAl = bOff + 1 * TILEB;
        const uint32_t aBh = bOff + 2 * TILEB;

        #pragma unroll
        for (int ks = 0; ks < 2; ks++) {
            const uint32_t kcol = (uint32_t)ks * 32;
            uint32_t bh[4][2];
            #pragma unroll
            for (int nf = 0; nf < 4; nf++) {
                uint32_t brow = wn * 32 + nf * 8 + (lane & 7);
                uint32_t boff = brow * PITCH + kcol + (((uint32_t)lane >> 3) & 1) * 16;
                LDSM_X2(bh[nf][0], bh[nf][1], aBh + boff);
            }
            #pragma unroll
            for (int mf = 0; mf < 4; mf++) {
                uint32_t arow = wm * 64 + mf * 16 + (lane & 15);
                uint32_t aoff = arow * PITCH + kcol + ((uint32_t)lane >> 4) * 16;
                uint32_t ah[4], al[4];
                LDSM_X4(ah[0], ah[1], ah[2], ah[3], aAh + aoff);
                LDSM_X4(al[0], al[1], al[2], al[3], aAl + aoff);
                #pragma unroll
                for (int nf = 0; nf < 4; nf++) {
                    MMA_FP16(acc[mf][nf], ah, bh[nf]);
                    MMA_FP16(acc[mf][nf], al, bh[nf]);
                }
            }
        }
        __syncthreads();
    }

    const int er = rowBase + wm * 64 + (lane >> 2);
    const int ec = colBase + wn * 32 + (lane & 3) * 2;
    #pragma unroll
    for (int mf = 0; mf < 4; mf++) {
        #pragma unroll
        for (int nf = 0; nf < 4; nf++) {
            int row = er + mf * 16;
            int col = ec + nf * 8;
            float b0 = bias[col], b1 = bias[col + 1];
            *(float2*)&C[(size_t)row * N + col] =
                make_float2(acc[mf][nf][0] + b0, acc[mf][nf][1] + b1);
            *(float2*)&C[(size_t)(row + 8) * N + col] =
                make_float2(acc[mf][nf][2] + b0, acc[mf][nf][3] + b1);
        }
    }
}

// ===========================================================================
// Per (graph, head) attention (R6 version + float4 global loads only)
// ===========================================================================
__global__ void __launch_bounds__(256) attn_kernel()
{
    extern __shared__ float sm[];
    float* Qs = sm;
    float* Ks = sm + 1 * 64 * PADROW;
    float* Vs = sm + 2 * 64 * PADROW;
    float* Ss = sm + 3 * 64 * PADROW;

    int h = blockIdx.x;
    int g = blockIdx.y;
    int tid = threadIdx.x;

    size_t base = (size_t)g * NPG * EQKV + (size_t)h * HD;

    // vectorized load: 1024 float4 elements (4 iters of 256 threads)
    for (int i = tid; i < NPG * HD / 4; i += 256) {
        int n = i >> 4;            // (i*4)>>6
        int d = (i & 15) * 4;      // (i*4)&63
        size_t src = base + (size_t)n * EQKV + d;
        float4 q = *(const float4*)&g_qkv[src];
        float4 k = *(const float4*)&g_qkv[src + DMODEL];
        float4 v = *(const float4*)&g_qkv[src + 2 * DMODEL];
        float* qd = &Qs[n * PADROW + d];
        float* kd = &Ks[n * PADROW + d];
        float* vd = &Vs[n * PADROW + d];
        qd[0] = q.x; qd[1] = q.y; qd[2] = q.z; qd[3] = q.w;
        kd[0] = k.x; kd[1] = k.y; kd[2] = k.z; kd[3] = k.w;
        vd[0] = v.x; vd[1] = v.y; vd[2] = v.z; vd[3] = v.w;
    }
    __syncthreads();

    int tx = tid & 15, ty = tid >> 4;
    int n0 = ty * 4, m0 = tx * 4;

    {
        float c[4][4];
        #pragma unroll
        for (int i = 0; i < 4; i++)
            #pragma unroll
            for (int j = 0; j < 4; j++) c[i][j] = 0.f;
        for (int d = 0; d < HD; d++) {
            float a[4], b[4];
            #pragma unroll
            for (int i = 0; i < 4; i++) a[i] = Qs[(n0 + i) * PADROW + d];
            #pragma unroll
            for (int j = 0; j < 4; j++) b[j] = Ks[(m0 + j) * PADROW + d];
            #pragma unroll
            for (int i = 0; i < 4; i++)
                #pragma unroll
                for (int j = 0; j < 4; j++)
                    c[i][j] = fmaf(a[i], b[j], c[i][j]);
        }
        #pragma unroll
        for (int i = 0; i < 4; i++)
            #pragma unroll
            for (int j = 0; j < 4; j++)
                Ss[(n0 + i) * PADROW + m0 + j] = c[i][j] * 0.125f;
    }
    __syncthreads();

    {
        int warp = tid >> 5, lane = tid & 31;
        for (int r = 0; r < 8; r++) {
            int n = warp * 8 + r;
            float v0 = Ss[n * PADROW + lane];
            float v1 = Ss[n * PADROW + lane + 32];
            float mx = fmaxf(v0, v1);
            #pragma unroll
            for (int o = 16; o > 0; o >>= 1)
                mx = fmaxf(mx, __shfl_xor_sync(0xffffffffu, mx, o));
            float e0 = __expf(v0 - mx);
            float e1 = __expf(v1 - mx);
            float s = e0 + e1;
            #pragma unroll
            for (int o = 16; o > 0; o >>= 1)
                s += __shfl_xor_sync(0xffffffffu, s, o);
            float inv = 1.f / s;
            Ss[n * PADROW + lane]      = e0 * inv;
            Ss[n * PADROW + lane + 32] = e1 * inv;
        }
    }
    __syncthreads();

    {
        float c[4][4];
        #pragma unroll
        for (int i = 0; i < 4; i++)
            #pragma unroll
            for (int j = 0; j < 4; j++) c[i][j] = 0.f;
        for (int m = 0; m < NPG; m++) {
            float a[4], b[4];
            #pragma unroll
            for (int i = 0; i < 4; i++) a[i] = Ss[(n0 + i) * PADROW + m];
            #pragma unroll
            for (int j = 0; j < 4; j++) b[j] = Vs[m * PADROW + m0 + j];
            #pragma unroll
            for (int i = 0; i < 4; i++)
                #pragma unroll
                for (int j = 0; j < 4; j++)
                    c[i][j] = fmaf(a[i], b[j], c[i][j]);
        }
        #pragma unroll
        for (int i = 0; i < 4; i++) {
            size_t row = (size_t)(g * NPG + n0 + i) * DMODEL + h * HD + m0;
            #pragma unroll
            for (int j = 0; j < 4; j++) {
                float v = c[i][j];
                __half hh = __float2half(v);
                g_ctxh[row + j] = hh;
                g_ctxl[row + j] = __float2half(v - __half2float(hh));
            }
        }
    }
}

// ===========================================================================
// Per-graph gate + reduction
// ===========================================================================
__global__ void __launch_bounds__(256) gate_reduce(
    const float* __restrict__ gw, const float* __restrict__ gb,
    float* __restrict__ out)
{
    __shared__ float gates[NPG];
    int g = blockIdx.x;
    const float* base = g_att + (size_t)g * NPG * DMODEL;

    int warp = threadIdx.x >> 5, lane = threadIdx.x & 31;
    for (int r = 0; r < 8; r++) {
        int n = warp * 8 + r;
        const float* row = base + (size_t)n * DMODEL;
        float s = 0.f;
        #pragma unroll
        for (int c = 0; c < DMODEL / 32; c++)
            s = fmaf(row[lane + c * 32], gw[lane + c * 32], s);
        #pragma unroll
        for (int o = 16; o > 0; o >>= 1)
            s += __shfl_xor_sync(0xffffffffu, s, o);
        if (lane == 0)
            gates[n] = 1.f / (1.f + __expf(-(s + gb[0])));
    }
    __syncthreads();

    for (int c = threadIdx.x; c < DMODEL; c += 256) {
        float acc = 0.f;
        #pragma unroll 8
        for (int n = 0; n < NPG; n++)
            acc = fmaf(gates[n], base[(size_t)n * DMODEL + c], acc);
        out[(size_t)g * DMODEL + c] = acc;
    }
}

// ===========================================================================
extern "C" void kernel_launch(void* const* d_in, const int* in_sizes, int n_in,
                              void* d_out, int out_size)
{
    const float* x      = (const float*)d_in[0];
    const float* in_w   = (const float*)d_in[2];
    const float* in_b   = (const float*)d_in[3];
    const float* out_w  = (const float*)d_in[4];
    const float* out_b  = (const float*)d_in[5];
    const float* gate_w = (const float*)d_in[6];
    const float* gate_b = (const float*)d_in[7];
    float* out          = (float*)d_out;

    float *qkv, *att;
    __half *xh, *xl, *ctxh, *ctxl, *inwh, *outwh;
    cudaGetSymbolAddress((void**)&qkv, g_qkv);
    cudaGetSymbolAddress((void**)&att, g_att);
    cudaGetSymbolAddress((void**)&xh, g_xh);
    cudaGetSymbolAddress((void**)&xl, g_xl);
    cudaGetSymbolAddress((void**)&ctxh, g_ctxh);
    cudaGetSymbolAddress((void**)&ctxl, g_ctxl);
    cudaGetSymbolAddress((void**)&inwh, g_inwh);
    cudaGetSymbolAddress((void**)&outwh, g_outwh);

    const int smem_attn = 4 * 64 * PADROW * sizeof(float);
    cudaFuncSetAttribute(attn_kernel,
                         cudaFuncAttributeMaxDynamicSharedMemorySize, smem_attn);
    cudaFuncSetAttribute(gemm_fp16,
                         cudaFuncAttributeMaxDynamicSharedMemorySize, GEMM_SMEM);

    // 0) operand conversion
    {
        size_t n4 = (size_t)TOTAL * DMODEL / 4;
        split_fp16<<<(unsigned)((n4 + 255) / 256), 256>>>(x, xh, xl, n4);
        size_t w4 = (size_t)EQKV * DMODEL / 4;
        cvt_fp16<<<(unsigned)((w4 + 255) / 256), 256>>>(in_w, inwh, w4);
        size_t o4 = (size_t)DMODEL * DMODEL / 4;
        cvt_fp16<<<(unsigned)((o4 + 255) / 256), 256>>>(out_w, outwh, o4);
    }

    // 1) QKV projection
    gemm_fp16<<<dim3(EQKV / 128, TOTAL / 128), 256, GEMM_SMEM>>>(
        xh, xl, inwh, in_b, qkv, EQKV, DMODEL);

    // 2) attention (fp32, emits ctx pre-split fp16)
    attn_kernel<<<dim3(NHEAD, NGRAPH), 256, smem_attn>>>();

    // 3) output projection
    gemm_fp16<<<dim3(DMODEL / 128, TOTAL / 128), 256, GEMM_SMEM>>>(
        ctxh, ctxl, outwh, out_b, att, DMODEL, DMODEL);

    // 4) gate + per-graph reduction
    gate_reduce<<<NGRAPH, 256>>>(gate_w, gate_b, out);
}

// round 14
// speedup vs baseline: 1.6901x; 1.0926x over previous
#include <cuda_runtime.h>
#include <cuda_fp16.h>
#include <math.h>
#include <stdint.h>

#define TOTAL 65536
#define DMODEL 512
#define EQKV   1536
#define NGRAPH 1024
#define NPG    64
#define NHEAD  8
#define HD     64
#define PADROW 65

// ------------------------------- scratch ----------------------------------
__device__ float g_qkv[(size_t)TOTAL * EQKV];
__device__ float g_att[(size_t)TOTAL * DMODEL];
__device__ __half g_xh[(size_t)TOTAL * DMODEL];
__device__ __half g_xl[(size_t)TOTAL * DMODEL];
__device__ __half g_ctxh[(size_t)TOTAL * DMODEL];
__device__ __half g_inwh[(size_t)EQKV * DMODEL];
__device__ __half g_outwh[(size_t)DMODEL * DMODEL];

// ------------------------------ PTX helpers -------------------------------
__device__ __forceinline__ uint32_t smem_u32(const void* p) {
    uint32_t a;
    asm("{ .reg .u64 t; cvta.to.shared.u64 t, %1; cvt.u32.u64 %0, t; }"
        : "=r"(a) : "l"(p));
    return a;
}
#define LDSM_X4(r0, r1, r2, r3, addr) \
    asm volatile("ldmatrix.sync.aligned.m8n8.x4.shared.b16 {%0,%1,%2,%3}, [%4];" \
        : "=r"(r0), "=r"(r1), "=r"(r2), "=r"(r3) : "r"(addr))
#define LDSM_X2(r0, r1, addr) \
    asm volatile("ldmatrix.sync.aligned.m8n8.x2.shared.b16 {%0,%1}, [%2];" \
        : "=r"(r0), "=r"(r1) : "r"(addr))
#define MMA_FP16(d, a, b) \
    asm volatile("mma.sync.aligned.m16n8k16.row.col.f32.f16.f16.f32 " \
        "{%0,%1,%2,%3}, {%4,%5,%6,%7}, {%8,%9}, {%0,%1,%2,%3};" \
        : "+f"((d)[0]), "+f"((d)[1]), "+f"((d)[2]), "+f"((d)[3]) \
        : "r"((a)[0]), "r"((a)[1]), "r"((a)[2]), "r"((a)[3]), \
          "r"((b)[0]), "r"((b)[1]))
#define CP_ASYNC16(dst, src) \
    asm volatile("cp.async.cg.shared.global [%0], [%1], 16;" \
        :: "r"(dst), "l"(src) : "memory")
#define CP_COMMIT() asm volatile("cp.async.commit_group;" ::: "memory")
#define CP_WAIT(n)  asm volatile("cp.async.wait_group %0;" :: "n"(n) : "memory")

// --------------------------- conversion kernels ---------------------------
__global__ void __launch_bounds__(256) split_fp16(
    const float* __restrict__ src, __half* __restrict__ hi,
    __half* __restrict__ lo, size_t n4)
{
    size_t i = (size_t)blockIdx.x * 256 + threadIdx.x;
    if (i >= n4) return;
    float4 v = ((const float4*)src)[i];
    __half h0 = __float2half(v.x), h1 = __float2half(v.y);
    __half h2 = __float2half(v.z), h3 = __float2half(v.w);
    __half2 H0(h0, h1), H1(h2, h3);
    __half2 L0(__float2half(v.x - __half2float(h0)),
               __float2half(v.y - __half2float(h1)));
    __half2 L1(__float2half(v.z - __half2float(h2)),
               __float2half(v.w - __half2float(h3)));
    ((uint2*)hi)[i] = make_uint2(*(uint32_t*)&H0, *(uint32_t*)&H1);
    ((uint2*)lo)[i] = make_uint2(*(uint32_t*)&L0, *(uint32_t*)&L1);
}

__global__ void __launch_bounds__(256) cvt_fp16(
    const float* __restrict__ src, __half* __restrict__ dst, size_t n4)
{
    size_t i = (size_t)blockIdx.x * 256 + threadIdx.x;
    if (i >= n4) return;
    float4 v = ((const float4*)src)[i];
    __half2 H0(__float2half(v.x), __float2half(v.y));
    __half2 H1(__float2half(v.z), __float2half(v.w));
    ((uint2*)dst)[i] = make_uint2(*(uint32_t*)&H0, *(uint32_t*)&H1);
}

// ===========================================================================
// 2-pass fp16 mma.sync GEMM (EXACT R6 version — frozen; used for QKV)
// ===========================================================================
#define PITCH 80
#define TILEB (128 * PITCH)
#define BUFB  (3 * TILEB)
#define GEMM_SMEM (2 * BUFB)

__global__ void __launch_bounds__(256, 2) gemm_fp16(
    const __half* __restrict__ Ah, const __half* __restrict__ Al,
    const __half* __restrict__ Bh,
    const float* __restrict__ bias, float* __restrict__ C,
    int N, int K)
{
    extern __shared__ __align__(16) uint8_t smem[];
    const uint32_t smBase = smem_u32(smem);

    const int tid  = threadIdx.x;
    const int wid  = tid >> 5;
    const int lane = tid & 31;
    const int wm   = wid >> 2;
    const int wn   = wid & 3;
    const int rowBase = blockIdx.y * 128;
    const int colBase = blockIdx.x * 128;

    const int g0 = tid * 2;
    const int r0g = g0 >> 2, c0g = g0 & 3;
    const int g1 = tid * 2 + 1;
    const int r1g = g1 >> 2, c1g = g1 & 3;

    const __half* pAh = Ah + (size_t)rowBase * K;
    const __half* pAl = Al + (size_t)rowBase * K;
    const __half* pBh = Bh + (size_t)colBase * K;

    const int NC = K >> 5;

    auto loadChunk = [&](int c) {
        const int k0 = c << 5;
        const uint32_t bOff = smBase + (c & 1) * BUFB;
        const uint32_t d0 = (uint32_t)(r0g * PITCH + c0g * 16);
        const uint32_t d1 = (uint32_t)(r1g * PITCH + c1g * 16);
        const size_t s0 = (size_t)r0g * K + k0 + c0g * 8;
        const size_t s1 = (size_t)r1g * K + k0 + c1g * 8;
        CP_ASYNC16(bOff + 0 * TILEB + d0, pAh + s0);
        CP_ASYNC16(bOff + 0 * TILEB + d1, pAh + s1);
        CP_ASYNC16(bOff + 1 * TILEB + d0, pAl + s0);
        CP_ASYNC16(bOff + 1 * TILEB + d1, pAl + s1);
        CP_ASYNC16(bOff + 2 * TILEB + d0, pBh + s0);
        CP_ASYNC16(bOff + 2 * TILEB + d1, pBh + s1);
    };

    float acc[4][4][4];
    #pragma unroll
    for (int mf = 0; mf < 4; mf++)
        #pragma unroll
        for (int nf = 0; nf < 4; nf++)
            #pragma unroll
            for (int e = 0; e < 4; e++) acc[mf][nf][e] = 0.f;

    loadChunk(0);
    CP_COMMIT();

    for (int c = 0; c < NC; c++) {
        if (c + 1 < NC) {
            loadChunk(c + 1);
            CP_COMMIT();
            CP_WAIT(1);
        } else {
            CP_WAIT(0);
        }
        __syncthreads();

        const uint32_t bOff = smBase + (c & 1) * BUFB;
        const uint32_t aAh = bOff;
        const uint32_t aAl = bOff + 1 * TILEB;
        const uint32_t aBh = bOff + 2 * TILEB;

        #pragma unroll
        for (int ks = 0; ks < 2; ks++) {
            const uint32_t kcol = (uint32_t)ks * 32;
            uint32_t bh[4][2];
            #pragma unroll
            for (int nf = 0; nf < 4; nf++) {
                uint32_t brow = wn * 32 + nf * 8 + (lane & 7);
                uint32_t boff = brow * PITCH + kcol + (((uint32_t)lane >> 3) & 1) * 16;
                LDSM_X2(bh[nf][0], bh[nf][1], aBh + boff);
            }
            #pragma unroll
            for (int mf = 0; mf < 4; mf++) {
                uint32_t arow = wm * 64 + mf * 16 + (lane & 15);
                uint32_t aoff = arow * PITCH + kcol + ((uint32_t)lane >> 4) * 16;
                uint32_t ah[4], al[4];
                LDSM_X4(ah[0], ah[1], ah[2], ah[3], aAh + aoff);
                LDSM_X4(al[0], al[1], al[2], al[3], aAl + aoff);
                #pragma unroll
                for (int nf = 0; nf < 4; nf++) {
                    MMA_FP16(acc[mf][nf], ah, bh[nf]);
                    MMA_FP16(acc[mf][nf], al, bh[nf]);
                }
            }
        }
        __syncthreads();
    }

    const int er = rowBase + wm * 64 + (lane >> 2);
    const int ec = colBase + wn * 32 + (lane & 3) * 2;
    #pragma unroll
    for (int mf = 0; mf < 4; mf++) {
        #pragma unroll
        for (int nf = 0; nf < 4; nf++) {
            int row = er + mf * 16;
            int col = ec + nf * 8;
            float b0 = bias[col], b1 = bias[col + 1];
            *(float2*)&C[(size_t)row * N + col] =
                make_float2(acc[mf][nf][0] + b0, acc[mf][nf][1] + b1);
            *(float2*)&C[(size_t)(row + 8) * N + col] =
                make_float2(acc[mf][nf][2] + b0, acc[mf][nf][3] + b1);
        }
    }
}

// ===========================================================================
// 1-pass fp16 mma.sync GEMM (A hi only) — used for output projection.
// Same tile/pipeline as gemm_fp16, minus the Al tile and residual MMAs.
// ===========================================================================
#define BUFB1 (2 * TILEB)           // Ah, Bh = 20480 B per stage
#define GEMM1P_SMEM (2 * BUFB1)     // 40960 B

__global__ void __launch_bounds__(256, 2) gemm_fp16_1p(
    const __half* __restrict__ Ah,
    const __half* __restrict__ Bh,
    const float* __restrict__ bias, float* __restrict__ C,
    int N, int K)
{
    extern __shared__ __align__(16) uint8_t smem[];
    const uint32_t smBase = smem_u32(smem);

    const int tid  = threadIdx.x;
    const int wid  = tid >> 5;
    const int lane = tid & 31;
    const int wm   = wid >> 2;
    const int wn   = wid & 3;
    const int rowBase = blockIdx.y * 128;
    const int colBase = blockIdx.x * 128;

    const int g0 = tid * 2;
    const int r0g = g0 >> 2, c0g = g0 & 3;
    const int g1 = tid * 2 + 1;
    const int r1g = g1 >> 2, c1g = g1 & 3;

    const __half* pAh = Ah + (size_t)rowBase * K;
    const __half* pBh = Bh + (size_t)colBase * K;

    const int NC = K >> 5;

    auto loadChunk = [&](int c) {
        const int k0 = c << 5;
        const uint32_t bOff = smBase + (c & 1) * BUFB1;
        const uint32_t d0 = (uint32_t)(r0g * PITCH + c0g * 16);
        const uint32_t d1 = (uint32_t)(r1g * PITCH + c1g * 16);
        const size_t s0 = (size_t)r0g * K + k0 + c0g * 8;
        const size_t s1 = (size_t)r1g * K + k0 + c1g * 8;
        CP_ASYNC16(bOff + 0 * TILEB + d0, pAh + s0);
        CP_ASYNC16(bOff + 0 * TILEB + d1, pAh + s1);
        CP_ASYNC16(bOff + 1 * TILEB + d0, pBh + s0);
        CP_ASYNC16(bOff + 1 * TILEB + d1, pBh + s1);
    };

    float acc[4][4][4];
    #pragma unroll
    for (int mf = 0; mf < 4; mf++)
        #pragma unroll
        for (int nf = 0; nf < 4; nf++)
            #pragma unroll
            for (int e = 0; e < 4; e++) acc[mf][nf][e] = 0.f;

    loadChunk(0);
    CP_COMMIT();

    for (int c = 0; c < NC; c++) {
        if (c + 1 < NC) {
            loadChunk(c + 1);
            CP_COMMIT();
            CP_WAIT(1);
        } else {
            CP_WAIT(0);
        }
        __syncthreads();

        const uint32_t bOff = smBase + (c & 1) * BUFB1;
        const uint32_t aAh = bOff;
        const uint32_t aBh = bOff + 1 * TILEB;

        #pragma unroll
        for (int ks = 0; ks < 2; ks++) {
            const uint32_t kcol = (uint32_t)ks * 32;
            uint32_t bh[4][2];
            #pragma unroll
            for (int nf = 0; nf < 4; nf++) {
                uint32_t brow = wn * 32 + nf * 8 + (lane & 7);
                uint32_t boff = brow * PITCH + kcol + (((uint32_t)lane >> 3) & 1) * 16;
                LDSM_X2(bh[nf][0], bh[nf][1], aBh + boff);
            }
            #pragma unroll
            for (int mf = 0; mf < 4; mf++) {
                uint32_t arow = wm * 64 + mf * 16 + (lane & 15);
                uint32_t aoff = arow * PITCH + kcol + ((uint32_t)lane >> 4) * 16;
                uint32_t ah[4];
                LDSM_X4(ah[0], ah[1], ah[2], ah[3], aAh + aoff);
                #pragma unroll
                for (int nf = 0; nf < 4; nf++) {
                    MMA_FP16(acc[mf][nf], ah, bh[nf]);
                }
            }
        }
        __syncthreads();
    }

    const int er = rowBase + wm * 64 + (lane >> 2);
    const int ec = colBase + wn * 32 + (lane & 3) * 2;
    #pragma unroll
    for (int mf = 0; mf < 4; mf++) {
        #pragma unroll
        for (int nf = 0; nf < 4; nf++) {
            int row = er + mf * 16;
            int col = ec + nf * 8;
            float b0 = bias[col], b1 = bias[col + 1];
            *(float2*)&C[(size_t)row * N + col] =
                make_float2(acc[mf][nf][0] + b0, acc[mf][nf][1] + b1);
            *(float2*)&C[(size_t)(row + 8) * N + col] =
                make_float2(acc[mf][nf][2] + b0, acc[mf][nf][3] + b1);
        }
    }
}

// ===========================================================================
// Per (graph, head) attention (R13 version; ctx emitted fp16 hi only)
// ===========================================================================
__global__ void __launch_bounds__(256) attn_kernel()
{
    extern __shared__ float sm[];
    float* Qs = sm;
    float* Ks = sm + 1 * 64 * PADROW;
    float* Vs = sm + 2 * 64 * PADROW;
    float* Ss = sm + 3 * 64 * PADROW;

    int h = blockIdx.x;
    int g = blockIdx.y;
    int tid = threadIdx.x;

    size_t base = (size_t)g * NPG * EQKV + (size_t)h * HD;

    for (int i = tid; i < NPG * HD / 4; i += 256) {
        int n = i >> 4;
        int d = (i & 15) * 4;
        size_t src = base + (size_t)n * EQKV + d;
        float4 q = *(const float4*)&g_qkv[src];
        float4 k = *(const float4*)&g_qkv[src + DMODEL];
        float4 v = *(const float4*)&g_qkv[src + 2 * DMODEL];
        float* qd = &Qs[n * PADROW + d];
        float* kd = &Ks[n * PADROW + d];
        float* vd = &Vs[n * PADROW + d];
        qd[0] = q.x; qd[1] = q.y; qd[2] = q.z; qd[3] = q.w;
        kd[0] = k.x; kd[1] = k.y; kd[2] = k.z; kd[3] = k.w;
        vd[0] = v.x; vd[1] = v.y; vd[2] = v.z; vd[3] = v.w;
    }
    __syncthreads();

    int tx = tid & 15, ty = tid >> 4;
    int n0 = ty * 4, m0 = tx * 4;

    {
        float c[4][4];
        #pragma unroll
        for (int i = 0; i < 4; i++)
            #pragma unroll
            for (int j = 0; j < 4; j++) c[i][j] = 0.f;
        for (int d = 0; d < HD; d++) {
            float a[4], b[4];
            #pragma unroll
            for (int i = 0; i < 4; i++) a[i] = Qs[(n0 + i) * PADROW + d];
            #pragma unroll
            for (int j = 0; j < 4; j++) b[j] = Ks[(m0 + j) * PADROW + d];
            #pragma unroll
            for (int i = 0; i < 4; i++)
                #pragma unroll
                for (int j = 0; j < 4; j++)
                    c[i][j] = fmaf(a[i], b[j], c[i][j]);
        }
        #pragma unroll
        for (int i = 0; i < 4; i++)
            #pragma unroll
            for (int j = 0; j < 4; j++)
                Ss[(n0 + i) * PADROW + m0 + j] = c[i][j] * 0.125f;
    }
    __syncthreads();

    {
        int warp = tid >> 5, lane = tid & 31;
        for (int r = 0; r < 8; r++) {
            int n = warp * 8 + r;
            float v0 = Ss[n * PADROW + lane];
            float v1 = Ss[n * PADROW + lane + 32];
            float mx = fmaxf(v0, v1);
            #pragma unroll
            for (int o = 16; o > 0; o >>= 1)
                mx = fmaxf(mx, __shfl_xor_sync(0xffffffffu, mx, o));
            float e0 = __expf(v0 - mx);
            float e1 = __expf(v1 - mx);
            float s = e0 + e1;
            #pragma unroll
            for (int o = 16; o > 0; o >>= 1)
                s += __shfl_xor_sync(0xffffffffu, s, o);
            float inv = 1.f / s;
            Ss[n * PADROW + lane]      = e0 * inv;
            Ss[n * PADROW + lane + 32] = e1 * inv;
        }
    }
    __syncthreads();

    {
        float c[4][4];
        #pragma unroll
        for (int i = 0; i < 4; i++)
            #pragma unroll
            for (int j = 0; j < 4; j++) c[i][j] = 0.f;
        for (int m = 0; m < NPG; m++) {
            float a[4], b[4];
            #pragma unroll
            for (int i = 0; i < 4; i++) a[i] = Ss[(n0 + i) * PADROW + m];
            #pragma unroll
            for (int j = 0; j < 4; j++) b[j] = Vs[m * PADROW + m0 + j];
            #pragma unroll
            for (int i = 0; i < 4; i++)
                #pragma unroll
                for (int j = 0; j < 4; j++)
                    c[i][j] = fmaf(a[i], b[j], c[i][j]);
        }
        #pragma unroll
        for (int i = 0; i < 4; i++) {
            size_t row = (size_t)(g * NPG + n0 + i) * DMODEL + h * HD + m0;
            __half2 h01(__float2half(c[i][0]), __float2half(c[i][1]));
            __half2 h23(__float2half(c[i][2]), __float2half(c[i][3]));
            *(__half2*)&g_ctxh[row]     = h01;
            *(__half2*)&g_ctxh[row + 2] = h23;
        }
    }
}

// ===========================================================================
// Per-graph gate + reduction
// ===========================================================================
__global__ void __launch_bounds__(256) gate_reduce(
    const float* __restrict__ gw, const float* __restrict__ gb,
    float* __restrict__ out)
{
    __shared__ float gates[NPG];
    int g = blockIdx.x;
    const float* base = g_att + (size_t)g * NPG * DMODEL;

    int warp = threadIdx.x >> 5, lane = threadIdx.x & 31;
    for (int r = 0; r < 8; r++) {
        int n = warp * 8 + r;
        const float* row = base + (size_t)n * DMODEL;
        float s = 0.f;
        #pragma unroll
        for (int c = 0; c < DMODEL / 32; c++)
            s = fmaf(row[lane + c * 32], gw[lane + c * 32], s);
        #pragma unroll
        for (int o = 16; o > 0; o >>= 1)
            s += __shfl_xor_sync(0xffffffffu, s, o);
        if (lane == 0)
            gates[n] = 1.f / (1.f + __expf(-(s + gb[0])));
    }
    __syncthreads();

    for (int c = threadIdx.x; c < DMODEL; c += 256) {
        float acc = 0.f;
        #pragma unroll 8
        for (int n = 0; n < NPG; n++)
            acc = fmaf(gates[n], base[(size_t)n * DMODEL + c], acc);
        out[(size_t)g * DMODEL + c] = acc;
    }
}

// ===========================================================================
extern "C" void kernel_launch(void* const* d_in, const int* in_sizes, int n_in,
                              void* d_out, int out_size)
{
    const float* x      = (const float*)d_in[0];
    const float* in_w   = (const float*)d_in[2];
    const float* in_b   = (const float*)d_in[3];
    const float* out_w  = (const float*)d_in[4];
    const float* out_b  = (const float*)d_in[5];
    const float* gate_w = (const float*)d_in[6];
    const float* gate_b = (const float*)d_in[7];
    float* out          = (float*)d_out;

    float *qkv, *att;
    __half *xh, *xl, *ctxh, *inwh, *outwh;
    cudaGetSymbolAddress((void**)&qkv, g_qkv);
    cudaGetSymbolAddress((void**)&att, g_att);
    cudaGetSymbolAddress((void**)&xh, g_xh);
    cudaGetSymbolAddress((void**)&xl, g_xl);
    cudaGetSymbolAddress((void**)&ctxh, g_ctxh);
    cudaGetSymbolAddress((void**)&inwh, g_inwh);
    cudaGetSymbolAddress((void**)&outwh, g_outwh);

    const int smem_attn = 4 * 64 * PADROW * sizeof(float);
    cudaFuncSetAttribute(attn_kernel,
                         cudaFuncAttributeMaxDynamicSharedMemorySize, smem_attn);
    cudaFuncSetAttribute(gemm_fp16,
                         cudaFuncAttributeMaxDynamicSharedMemorySize, GEMM_SMEM);
    cudaFuncSetAttribute(gemm_fp16_1p,
                         cudaFuncAttributeMaxDynamicSharedMemorySize, GEMM1P_SMEM);

    // 0) operand conversion
    {
        size_t n4 = (size_t)TOTAL * DMODEL / 4;
        split_fp16<<<(unsigned)((n4 + 255) / 256), 256>>>(x, xh, xl, n4);
        size_t w4 = (size_t)EQKV * DMODEL / 4;
        cvt_fp16<<<(unsigned)((w4 + 255) / 256), 256>>>(in_w, inwh, w4);
        size_t o4 = (size_t)DMODEL * DMODEL / 4;
        cvt_fp16<<<(unsigned)((o4 + 255) / 256), 256>>>(out_w, outwh, o4);
    }

    // 1) QKV projection (2-pass, accuracy-critical)
    gemm_fp16<<<dim3(EQKV / 128, TOTAL / 128), 256, GEMM_SMEM>>>(
        xh, xl, inwh, in_b, qkv, EQKV, DMODEL);

    // 2) attention (fp32, emits ctx fp16 hi only)
    attn_kernel<<<dim3(NHEAD, NGRAPH), 256, smem_attn>>>();

    // 3) output projection (1-pass fp16)
    gemm_fp16_1p<<<dim3(DMODEL / 128, TOTAL / 128), 256, GEMM1P_SMEM>>>(
        ctxh, outwh, out_b, att, DMODEL, DMODEL);

    // 4) gate + per-graph reduction
    gate_reduce<<<NGRAPH, 256>>>(gate_w, gate_b, out);
}

// round 15
// speedup vs baseline: 2.0326x; 1.2027x over previous
#include <cuda_runtime.h>
#include <cuda_fp16.h>
#include <math.h>
#include <stdint.h>

#define TOTAL 65536
#define DMODEL 512
#define EQKV   1536
#define NGRAPH 1024
#define NPG    64
#define NHEAD  8
#define HD     64
#define PADROW 65

// ------------------------------- scratch ----------------------------------
__device__ float g_qkv[(size_t)TOTAL * EQKV];
__device__ float g_att[(size_t)TOTAL * DMODEL];
__device__ __half g_xh[(size_t)TOTAL * DMODEL];
__device__ __half g_ctxh[(size_t)TOTAL * DMODEL];
__device__ __half g_inwh[(size_t)EQKV * DMODEL];
__device__ __half g_outwh[(size_t)DMODEL * DMODEL];

// ------------------------------ PTX helpers -------------------------------
__device__ __forceinline__ uint32_t smem_u32(const void* p) {
    uint32_t a;
    asm("{ .reg .u64 t; cvta.to.shared.u64 t, %1; cvt.u32.u64 %0, t; }"
        : "=r"(a) : "l"(p));
    return a;
}
#define LDSM_X4(r0, r1, r2, r3, addr) \
    asm volatile("ldmatrix.sync.aligned.m8n8.x4.shared.b16 {%0,%1,%2,%3}, [%4];" \
        : "=r"(r0), "=r"(r1), "=r"(r2), "=r"(r3) : "r"(addr))
#define LDSM_X2(r0, r1, addr) \
    asm volatile("ldmatrix.sync.aligned.m8n8.x2.shared.b16 {%0,%1}, [%2];" \
        : "=r"(r0), "=r"(r1) : "r"(addr))
#define MMA_FP16(d, a, b) \
    asm volatile("mma.sync.aligned.m16n8k16.row.col.f32.f16.f16.f32 " \
        "{%0,%1,%2,%3}, {%4,%5,%6,%7}, {%8,%9}, {%0,%1,%2,%3};" \
        : "+f"((d)[0]), "+f"((d)[1]), "+f"((d)[2]), "+f"((d)[3]) \
        : "r"((a)[0]), "r"((a)[1]), "r"((a)[2]), "r"((a)[3]), \
          "r"((b)[0]), "r"((b)[1]))
#define CP_ASYNC16(dst, src) \
    asm volatile("cp.async.cg.shared.global [%0], [%1], 16;" \
        :: "r"(dst), "l"(src) : "memory")
#define CP_COMMIT() asm volatile("cp.async.commit_group;" ::: "memory")
#define CP_WAIT(n)  asm volatile("cp.async.wait_group %0;" :: "n"(n) : "memory")

// --------------------------- conversion kernel ----------------------------
__global__ void __launch_bounds__(256) cvt_fp16(
    const float* __restrict__ src, __half* __restrict__ dst, size_t n4)
{
    size_t i = (size_t)blockIdx.x * 256 + threadIdx.x;
    if (i >= n4) return;
    float4 v = ((const float4*)src)[i];
    __half2 H0(__float2half(v.x), __float2half(v.y));
    __half2 H1(__float2half(v.z), __float2half(v.w));
    ((uint2*)dst)[i] = make_uint2(*(uint32_t*)&H0, *(uint32_t*)&H1);
}

// ===========================================================================
// 1-pass fp16 mma.sync GEMM: C = A*B^T + bias (A, B both fp16-hi).
// 128x128 tile, 8 warps (2x4), K-chunk 32, cp.async double-buffered,
// pitch-80 smem, 2 CTAs/SM. (Validated as gemm_fp16_1p in R14.)
// ===========================================================================
#define PITCH 80
#define TILEB (128 * PITCH)
#define BUFB1 (2 * TILEB)           // Ah, Bh = 20480 B per stage
#define GEMM1P_SMEM (2 * BUFB1)     // 40960 B

__global__ void __launch_bounds__(256, 2) gemm_fp16_1p(
    const __half* __restrict__ Ah,
    const __half* __restrict__ Bh,
    const float* __restrict__ bias, float* __restrict__ C,
    int N, int K)
{
    extern __shared__ __align__(16) uint8_t smem[];
    const uint32_t smBase = smem_u32(smem);

    const int tid  = threadIdx.x;
    const int wid  = tid >> 5;
    const int lane = tid & 31;
    const int wm   = wid >> 2;
    const int wn   = wid & 3;
    const int rowBase = blockIdx.y * 128;
    const int colBase = blockIdx.x * 128;

    const int g0 = tid * 2;
    const int r0g = g0 >> 2, c0g = g0 & 3;
    const int g1 = tid * 2 + 1;
    const int r1g = g1 >> 2, c1g = g1 & 3;

    const __half* pAh = Ah + (size_t)rowBase * K;
    const __half* pBh = Bh + (size_t)colBase * K;

    const int NC = K >> 5;

    auto loadChunk = [&](int c) {
        const int k0 = c << 5;
        const uint32_t bOff = smBase + (c & 1) * BUFB1;
        const uint32_t d0 = (uint32_t)(r0g * PITCH + c0g * 16);
        const uint32_t d1 = (uint32_t)(r1g * PITCH + c1g * 16);
        const size_t s0 = (size_t)r0g * K + k0 + c0g * 8;
        const size_t s1 = (size_t)r1g * K + k0 + c1g * 8;
        CP_ASYNC16(bOff + 0 * TILEB + d0, pAh + s0);
        CP_ASYNC16(bOff + 0 * TILEB + d1, pAh + s1);
        CP_ASYNC16(bOff + 1 * TILEB + d0, pBh + s0);
        CP_ASYNC16(bOff + 1 * TILEB + d1, pBh + s1);
    };

    float acc[4][4][4];
    #pragma unroll
    for (int mf = 0; mf < 4; mf++)
        #pragma unroll
        for (int nf = 0; nf < 4; nf++)
            #pragma unroll
            for (int e = 0; e < 4; e++) acc[mf][nf][e] = 0.f;

    loadChunk(0);
    CP_COMMIT();

    for (int c = 0; c < NC; c++) {
        if (c + 1 < NC) {
            loadChunk(c + 1);
            CP_COMMIT();
            CP_WAIT(1);
        } else {
            CP_WAIT(0);
        }
        __syncthreads();

        const uint32_t bOff = smBase + (c & 1) * BUFB1;
        const uint32_t aAh = bOff;
        const uint32_t aBh = bOff + 1 * TILEB;

        #pragma unroll
        for (int ks = 0; ks < 2; ks++) {
            const uint32_t kcol = (uint32_t)ks * 32;
            uint32_t bh[4][2];
            #pragma unroll
            for (int nf = 0; nf < 4; nf++) {
                uint32_t brow = wn * 32 + nf * 8 + (lane & 7);
                uint32_t boff = brow * PITCH + kcol + (((uint32_t)lane >> 3) & 1) * 16;
                LDSM_X2(bh[nf][0], bh[nf][1], aBh + boff);
            }
            #pragma unroll
            for (int mf = 0; mf < 4; mf++) {
                uint32_t arow = wm * 64 + mf * 16 + (lane & 15);
                uint32_t aoff = arow * PITCH + kcol + ((uint32_t)lane >> 4) * 16;
                uint32_t ah[4];
                LDSM_X4(ah[0], ah[1], ah[2], ah[3], aAh + aoff);
                #pragma unroll
                for (int nf = 0; nf < 4; nf++) {
                    MMA_FP16(acc[mf][nf], ah, bh[nf]);
                }
            }
        }
        __syncthreads();
    }

    const int er = rowBase + wm * 64 + (lane >> 2);
    const int ec = colBase + wn * 32 + (lane & 3) * 2;
    #pragma unroll
    for (int mf = 0; mf < 4; mf++) {
        #pragma unroll
        for (int nf = 0; nf < 4; nf++) {
            int row = er + mf * 16;
            int col = ec + nf * 8;
            float b0 = bias[col], b1 = bias[col + 1];
            *(float2*)&C[(size_t)row * N + col] =
                make_float2(acc[mf][nf][0] + b0, acc[mf][nf][1] + b1);
            *(float2*)&C[(size_t)(row + 8) * N + col] =
                make_float2(acc[mf][nf][2] + b0, acc[mf][nf][3] + b1);
        }
    }
}

// ===========================================================================
// Per (graph, head) attention (R14 version; ctx emitted fp16 hi only)
// ===========================================================================
__global__ void __launch_bounds__(256) attn_kernel()
{
    extern __shared__ float sm[];
    float* Qs = sm;
    float* Ks = sm + 1 * 64 * PADROW;
    float* Vs = sm + 2 * 64 * PADROW;
    float* Ss = sm + 3 * 64 * PADROW;

    int h = blockIdx.x;
    int g = blockIdx.y;
    int tid = threadIdx.x;

    size_t base = (size_t)g * NPG * EQKV + (size_t)h * HD;

    for (int i = tid; i < NPG * HD / 4; i += 256) {
        int n = i >> 4;
        int d = (i & 15) * 4;
        size_t src = base + (size_t)n * EQKV + d;
        float4 q = *(const float4*)&g_qkv[src];
        float4 k = *(const float4*)&g_qkv[src + DMODEL];
        float4 v = *(const float4*)&g_qkv[src + 2 * DMODEL];
        float* qd = &Qs[n * PADROW + d];
        float* kd = &Ks[n * PADROW + d];
        float* vd = &Vs[n * PADROW + d];
        qd[0] = q.x; qd[1] = q.y; qd[2] = q.z; qd[3] = q.w;
        kd[0] = k.x; kd[1] = k.y; kd[2] = k.z; kd[3] = k.w;
        vd[0] = v.x; vd[1] = v.y; vd[2] = v.z; vd[3] = v.w;
    }
    __syncthreads();

    int tx = tid & 15, ty = tid >> 4;
    int n0 = ty * 4, m0 = tx * 4;

    {
        float c[4][4];
        #pragma unroll
        for (int i = 0; i < 4; i++)
            #pragma unroll
            for (int j = 0; j < 4; j++) c[i][j] = 0.f;
        for (int d = 0; d < HD; d++) {
            float a[4], b[4];
            #pragma unroll
            for (int i = 0; i < 4; i++) a[i] = Qs[(n0 + i) * PADROW + d];
            #pragma unroll
            for (int j = 0; j < 4; j++) b[j] = Ks[(m0 + j) * PADROW + d];
            #pragma unroll
            for (int i = 0; i < 4; i++)
                #pragma unroll
                for (int j = 0; j < 4; j++)
                    c[i][j] = fmaf(a[i], b[j], c[i][j]);
        }
        #pragma unroll
        for (int i = 0; i < 4; i++)
            #pragma unroll
            for (int j = 0; j < 4; j++)
                Ss[(n0 + i) * PADROW + m0 + j] = c[i][j] * 0.125f;
    }
    __syncthreads();

    {
        int warp = tid >> 5, lane = tid & 31;
        for (int r = 0; r < 8; r++) {
            int n = warp * 8 + r;
            float v0 = Ss[n * PADROW + lane];
            float v1 = Ss[n * PADROW + lane + 32];
            float mx = fmaxf(v0, v1);
            #pragma unroll
            for (int o = 16; o > 0; o >>= 1)
                mx = fmaxf(mx, __shfl_xor_sync(0xffffffffu, mx, o));
            float e0 = __expf(v0 - mx);
            float e1 = __expf(v1 - mx);
            float s = e0 + e1;
            #pragma unroll
            for (int o = 16; o > 0; o >>= 1)
                s += __shfl_xor_sync(0xffffffffu, s, o);
            float inv = 1.f / s;
            Ss[n * PADROW + lane]      = e0 * inv;
            Ss[n * PADROW + lane + 32] = e1 * inv;
        }
    }
    __syncthreads();

    {
        float c[4][4];
        #pragma unroll
        for (int i = 0; i < 4; i++)
            #pragma unroll
            for (int j = 0; j < 4; j++) c[i][j] = 0.f;
        for (int m = 0; m < NPG; m++) {
            float a[4], b[4];
            #pragma unroll
            for (int i = 0; i < 4; i++) a[i] = Ss[(n0 + i) * PADROW + m];
            #pragma unroll
            for (int j = 0; j < 4; j++) b[j] = Vs[m * PADROW + m0 + j];
            #pragma unroll
            for (int i = 0; i < 4; i++)
                #pragma unroll
                for (int j = 0; j < 4; j++)
                    c[i][j] = fmaf(a[i], b[j], c[i][j]);
        }
        #pragma unroll
        for (int i = 0; i < 4; i++) {
            size_t row = (size_t)(g * NPG + n0 + i) * DMODEL + h * HD + m0;
            __half2 h01(__float2half(c[i][0]), __float2half(c[i][1]));
            __half2 h23(__float2half(c[i][2]), __float2half(c[i][3]));
            *(__half2*)&g_ctxh[row]     = h01;
            *(__half2*)&g_ctxh[row + 2] = h23;
        }
    }
}

// ===========================================================================
// Per-graph gate + reduction
// ===========================================================================
__global__ void __launch_bounds__(256) gate_reduce(
    const float* __restrict__ gw, const float* __restrict__ gb,
    float* __restrict__ out)
{
    __shared__ float gates[NPG];
    int g = blockIdx.x;
    const float* base = g_att + (size_t)g * NPG * DMODEL;

    int warp = threadIdx.x >> 5, lane = threadIdx.x & 31;
    for (int r = 0; r < 8; r++) {
        int n = warp * 8 + r;
        const float* row = base + (size_t)n * DMODEL;
        float s = 0.f;
        #pragma unroll
        for (int c = 0; c < DMODEL / 32; c++)
            s = fmaf(row[lane + c * 32], gw[lane + c * 32], s);
        #pragma unroll
        for (int o = 16; o > 0; o >>= 1)
            s += __shfl_xor_sync(0xffffffffu, s, o);
        if (lane == 0)
            gates[n] = 1.f / (1.f + __expf(-(s + gb[0])));
    }
    __syncthreads();

    for (int c = threadIdx.x; c < DMODEL; c += 256) {
        float acc = 0.f;
        #pragma unroll 8
        for (int n = 0; n < NPG; n++)
            acc = fmaf(gates[n], base[(size_t)n * DMODEL + c], acc);
        out[(size_t)g * DMODEL + c] = acc;
    }
}

// ===========================================================================
extern "C" void kernel_launch(void* const* d_in, const int* in_sizes, int n_in,
                              void* d_out, int out_size)
{
    const float* x      = (const float*)d_in[0];
    const float* in_w   = (const float*)d_in[2];
    const float* in_b   = (const float*)d_in[3];
    const float* out_w  = (const float*)d_in[4];
    const float* out_b  = (const float*)d_in[5];
    const float* gate_w = (const float*)d_in[6];
    const float* gate_b = (const float*)d_in[7];
    float* out          = (float*)d_out;

    float *qkv, *att;
    __half *xh, *ctxh, *inwh, *outwh;
    cudaGetSymbolAddress((void**)&qkv, g_qkv);
    cudaGetSymbolAddress((void**)&att, g_att);
    cudaGetSymbolAddress((void**)&xh, g_xh);
    cudaGetSymbolAddress((void**)&ctxh, g_ctxh);
    cudaGetSymbolAddress((void**)&inwh, g_inwh);
    cudaGetSymbolAddress((void**)&outwh, g_outwh);

    const int smem_attn = 4 * 64 * PADROW * sizeof(float);
    cudaFuncSetAttribute(attn_kernel,
                         cudaFuncAttributeMaxDynamicSharedMemorySize, smem_attn);
    cudaFuncSetAttribute(gemm_fp16_1p,
                         cudaFuncAttributeMaxDynamicSharedMemorySize, GEMM1P_SMEM);

    // 0) operand conversion (all fp16-hi only)
    {
        size_t n4 = (size_t)TOTAL * DMODEL / 4;
        cvt_fp16<<<(unsigned)((n4 + 255) / 256), 256>>>(x, xh, n4);
        size_t w4 = (size_t)EQKV * DMODEL / 4;
        cvt_fp16<<<(unsigned)((w4 + 255) / 256), 256>>>(in_w, inwh, w4);
        size_t o4 = (size_t)DMODEL * DMODEL / 4;
        cvt_fp16<<<(unsigned)((o4 + 255) / 256), 256>>>(out_w, outwh, o4);
    }

    // 1) QKV projection (1-pass fp16)
    gemm_fp16_1p<<<dim3(EQKV / 128, TOTAL / 128), 256, GEMM1P_SMEM>>>(
        xh, inwh, in_b, qkv, EQKV, DMODEL);

    // 2) attention (fp32, emits ctx fp16 hi only)
    attn_kernel<<<dim3(NHEAD, NGRAPH), 256, smem_attn>>>();

    // 3) output projection (1-pass fp16)
    gemm_fp16_1p<<<dim3(DMODEL / 128, TOTAL / 128), 256, GEMM1P_SMEM>>>(
        ctxh, outwh, out_b, att, DMODEL, DMODEL);

    // 4) gate + per-graph reduction
    gate_reduce<<<NGRAPH, 256>>>(gate_w, gate_b, out);
}